// round 12
// baseline (speedup 1.0000x reference)
#include <cuda_runtime.h>
#include <cstdint>

#define D 128
#define N_MAX 50064
#define E_MAX 500000
#define FB 160          // fill blocks appended to kernel A
#define PREP_BLOCKS 256

// ---- device scratch (no allocations; .bss zero at load, kernels self-clean) ----
__device__ float g_h[(size_t)N_MAX * D];   // h' = dis[r]*(x@W)[r]; row N stays ZERO (pad row)
__device__ int   g_cnt[N_MAX];             // in-degree (excl. self); zeroed by k_final
__device__ float g_dis[N_MAX];             // rsqrt(1 + cnt)
__device__ int   g_start[N_MAX];
__device__ int   g_cursor[N_MAX];
__device__ int   g_adj[E_MAX];
__device__ int   g_total;                  // ticket; zeroed by k_final
__device__ int   g_arrive;                 // k_prep grid barrier; zeroed by k_final
__device__ float g_colstats[2 * D];        // zeroed by k_prep

// ---------------------------------------------------------------------------
// K1: fused count + alloc (grid barrier between phases; 256 blocks co-resident)
//   phase 1: in-degree count over pos edges; block 0 zeros colstats
//   phase 2: blocks [0, NB) do per-256-node scan + one atomic ticket
// ---------------------------------------------------------------------------
__global__ void __launch_bounds__(256) k_prep(const int* __restrict__ pos,
                                              int E, int N, int NB) {
    int b = blockIdx.x, t = threadIdx.x;
    if (b == 0) g_colstats[t] = 0.0f;                  // 256 == 2*D
    for (int e = b * 256 + t; e < E; e += PREP_BLOCKS * 256)
        atomicAdd(&g_cnt[pos[(size_t)E + e]], 1);

    // ---- grid barrier (256 small blocks always co-resident on 148 SMs) ----
    __threadfence();
    __syncthreads();
    if (t == 0) {
        atomicAdd(&g_arrive, 1);
        while (*(volatile int*)&g_arrive < PREP_BLOCKS) { }
    }
    __syncthreads();

    if (b >= NB) return;

    // ---- phase 2: segment allocation ----
    __shared__ int sh[256];
    __shared__ int base;
    int i = b * 256 + t;
    int c = (i < N) ? g_cnt[i] : 0;
    sh[t] = c;
    __syncthreads();
    for (int off = 1; off < 256; off <<= 1) {
        int v = (t >= off) ? sh[t - off] : 0;
        __syncthreads();
        sh[t] += v;
        __syncthreads();
    }
    if (t == 255) base = atomicAdd(&g_total, sh[255]);
    __syncthreads();
    if (i < N) {
        int start = base + sh[t] - c;
        g_start[i]  = start;
        g_cursor[i] = start;
        g_dis[i]    = rsqrtf(1.0f + (float)c);
    }
}

// ---------------------------------------------------------------------------
// Kernel A (block-specialized):
//   blocks [0, GB)     : h' = dis[r] * (x @ W)  (fp32x2 GEMM, 128x128 tile)
//   blocks [GB, GB+FB) : CSC adjacency fill (independent of h)
// ---------------------------------------------------------------------------
#define FMA2(acc, a, b) asm("fma.rn.f32x2 %0, %1, %2, %0;" : "+l"(acc) : "l"(a), "l"(b))

__global__ void __launch_bounds__(256) kA(const float* __restrict__ x,
                                          const float* __restrict__ W,
                                          const int* __restrict__ pos,
                                          int N, int E, int GB) {
    if (blockIdx.x >= GB) {
        // ---- fill path ----
        int b = blockIdx.x - GB;
        for (int e = b * 256 + threadIdx.x; e < E; e += FB * 256) {
            int col = pos[(size_t)E + e];
            int p = atomicAdd(&g_cursor[col], 1);
            g_adj[p] = pos[e];
        }
        return;
    }

    // ---- GEMM path ----
    __shared__ float xs[16][128];   // transposed x tile
    __shared__ float ws[16][128];   // W tile

    const int t  = threadIdx.x;
    const int r0 = blockIdx.x * 128;
    const int cg = t & 15;
    const int rg = t >> 4;

    unsigned long long acc[8][4];
#pragma unroll
    for (int i = 0; i < 8; i++)
#pragma unroll
        for (int j = 0; j < 4; j++) acc[i][j] = 0ull;

    for (int k0 = 0; k0 < D; k0 += 16) {
        __syncthreads();
#pragma unroll
        for (int u = 0; u < 2; u++) {
            int id  = t + u * 256;
            int row = id >> 2;
            int kq  = (id & 3) * 4;
            float4 v = make_float4(0.f, 0.f, 0.f, 0.f);
            int gr = r0 + row;
            if (gr < N) v = *(const float4*)(x + (size_t)gr * D + k0 + kq);
            xs[kq + 0][row] = v.x;
            xs[kq + 1][row] = v.y;
            xs[kq + 2][row] = v.z;
            xs[kq + 3][row] = v.w;
        }
#pragma unroll
        for (int u = 0; u < 2; u++) {
            int id = t + u * 256;
            int kk = id >> 5;
            int c4 = id & 31;
            *(float4*)&ws[kk][c4 * 4] =
                *(const float4*)(W + (size_t)(k0 + kk) * D + c4 * 4);
        }
        __syncthreads();

#pragma unroll
        for (int kk = 0; kk < 16; kk++) {
            ulonglong2 wA = *(const ulonglong2*)&ws[kk][cg * 8];
            ulonglong2 wB = *(const ulonglong2*)&ws[kk][cg * 8 + 4];
            float4 xa = *(const float4*)&xs[kk][rg * 8];
            float4 xb = *(const float4*)&xs[kk][rg * 8 + 4];
            float xv[8] = {xa.x, xa.y, xa.z, xa.w, xb.x, xb.y, xb.z, xb.w};
#pragma unroll
            for (int i = 0; i < 8; i++) {
                unsigned long long xd;
                asm("mov.b64 %0, {%1, %1};" : "=l"(xd) : "f"(xv[i]));
                FMA2(acc[i][0], xd, wA.x);
                FMA2(acc[i][1], xd, wA.y);
                FMA2(acc[i][2], xd, wB.x);
                FMA2(acc[i][3], xd, wB.y);
            }
        }
    }

#pragma unroll
    for (int i = 0; i < 8; i++) {
        int gr = r0 + rg * 8 + i;
        if (gr < N) {
            float s = g_dis[gr];
            float2 p0 = *(float2*)&acc[i][0];
            float2 p1 = *(float2*)&acc[i][1];
            float2 p2 = *(float2*)&acc[i][2];
            float2 p3 = *(float2*)&acc[i][3];
            *(float4*)(g_h + (size_t)gr * D + cg * 8) =
                make_float4(p0.x * s, p0.y * s, p1.x * s, p1.y * s);
            *(float4*)(g_h + (size_t)gr * D + cg * 8 + 4) =
                make_float4(p2.x * s, p2.y * s, p3.x * s, p3.y * s);
        }
    }
}

// ---------------------------------------------------------------------------
// K3: gather — one node per warp; tail handled by clamping pad lanes to the
//     permanently-zero row N of g_h (L1-hot, adds are no-ops). Pure v4 adds.
//     out[c] = dis[c] * (h'[c] + sum_in h'[r])
// ---------------------------------------------------------------------------
__global__ void __launch_bounds__(256, 6) k_gather(float* __restrict__ out, int N) {
    __shared__ float ssum[8][128];
    __shared__ float ssq[8][128];
    int lane = threadIdx.x & 31;
    int w    = threadIdx.x >> 5;

    float4 cs = make_float4(0.f, 0.f, 0.f, 0.f);
    float4 cq = make_float4(0.f, 0.f, 0.f, 0.f);

    for (int node = blockIdx.x * 8 + w; node < N; node += gridDim.x * 8) {
        int start = g_start[node];
        int cnt   = g_cnt[node];

        float4 acc = *(const float4*)(g_h + (size_t)node * D + lane * 4);  // self

        for (int j = 0; j < cnt; j += 32) {
            int m = min(32, cnt - j);
            int idx = (lane < m) ? g_adj[start + j + lane] : N;  // pad -> zero row
            for (int k = 0; k < m; k += 4) {   // 4-deep MLP; pads add zero
                int rA = __shfl_sync(0xffffffffu, idx, k + 0);
                int rB = __shfl_sync(0xffffffffu, idx, k + 1);
                int rC = __shfl_sync(0xffffffffu, idx, k + 2);
                int rD = __shfl_sync(0xffffffffu, idx, k + 3);
                float4 vA = *(const float4*)(g_h + (size_t)rA * D + lane * 4);
                float4 vB = *(const float4*)(g_h + (size_t)rB * D + lane * 4);
                float4 vC = *(const float4*)(g_h + (size_t)rC * D + lane * 4);
                float4 vD = *(const float4*)(g_h + (size_t)rD * D + lane * 4);
                acc.x += vA.x + vB.x + vC.x + vD.x;
                acc.y += vA.y + vB.y + vC.y + vD.y;
                acc.z += vA.z + vB.z + vC.z + vD.z;
                acc.w += vA.w + vB.w + vC.w + vD.w;
            }
        }

        float s = g_dis[node];
        float4 o = make_float4(acc.x * s, acc.y * s, acc.z * s, acc.w * s);
        *(float4*)(out + (size_t)node * D + lane * 4) = o;
        cs.x += o.x; cs.y += o.y; cs.z += o.z; cs.w += o.w;
        cq.x += o.x * o.x; cq.y += o.y * o.y;
        cq.z += o.z * o.z; cq.w += o.w * o.w;
    }

    *(float4*)&ssum[w][lane * 4] = cs;
    *(float4*)&ssq[w][lane * 4]  = cq;
    __syncthreads();
    int t = threadIdx.x;
    if (t < D) {
        float a = 0.f, b = 0.f;
#pragma unroll
        for (int w2 = 0; w2 < 8; w2++) { a += ssum[w2][t]; b += ssq[w2][t]; }
        atomicAdd(&g_colstats[t], a);
        atomicAdd(&g_colstats[D + t], b);
    }
}

// ---------------------------------------------------------------------------
// K4: BN (training mode, biased var) + ReLU in place; self-clean counters
// ---------------------------------------------------------------------------
__global__ void k_final(const float* __restrict__ gamma,
                        const float* __restrict__ beta,
                        float* __restrict__ out, int N) {
    __shared__ float sscale[D], sshift[D];
    int t = threadIdx.x;
    if (t < D) {
        float invN = 1.0f / (float)N;
        float mean = g_colstats[t] * invN;
        float var  = g_colstats[D + t] * invN - mean * mean;
        float inv  = rsqrtf(var + 1e-5f);
        float sc   = gamma[t] * inv;
        sscale[t]  = sc;
        sshift[t]  = beta[t] - mean * sc;
    }
    __syncthreads();

    int gid = blockIdx.x * blockDim.x + t;
    if (gid < N) g_cnt[gid] = 0;
    if (gid == 0) { g_total = 0; g_arrive = 0; }

    size_t total4 = (size_t)N * (D / 4);
    size_t stride = (size_t)gridDim.x * blockDim.x;
    for (size_t i = (size_t)blockIdx.x * blockDim.x + t; i < total4; i += stride) {
        int c = (int)(i & 31) * 4;
        float4 v = ((float4*)out)[i];
        v.x = fmaxf(v.x * sscale[c + 0] + sshift[c + 0], 0.0f);
        v.y = fmaxf(v.y * sscale[c + 1] + sshift[c + 1], 0.0f);
        v.z = fmaxf(v.z * sscale[c + 2] + sshift[c + 2], 0.0f);
        v.w = fmaxf(v.w * sscale[c + 3] + sshift[c + 3], 0.0f);
        ((float4*)out)[i] = v;
    }
}

// ---------------------------------------------------------------------------
extern "C" void kernel_launch(void* const* d_in, const int* in_sizes, int n_in,
                              void* d_out, int out_size) {
    const float* x     = (const float*)d_in[0];
    const int*   pos   = (const int*)d_in[1];   // int32 (JAX canonicalizes int64)
    // d_in[2] = neg_edge_index: weight 0 => no-op, skipped
    const float* W     = (const float*)d_in[3];
    // d_in[4] = b: cancels exactly inside BatchNorm, skipped
    const float* gamma = (const float*)d_in[5];
    const float* beta  = (const float*)d_in[6];
    float*       out   = (float*)d_out;

    const int N  = in_sizes[0] / D;
    const int E  = in_sizes[1] / 2;
    const int GB = (N + 127) / 128;
    const int NB = (N + 255) / 256;

    k_prep  <<<PREP_BLOCKS, 256>>>(pos, E, N, NB);
    kA      <<<GB + FB, 256>>>(x, W, pos, N, E, GB);
    k_gather<<<888, 256>>>(out, N);     // 148 SMs x 6 blocks
    k_final <<<784, 256>>>(gamma, beta, out, N);
}

// round 13
// speedup vs baseline: 1.1937x; 1.1937x over previous
#include <cuda_runtime.h>
#include <cuda_fp16.h>
#include <cstdint>

#define D 128
#define N_MAX 50064
#define E_MAX 500000
#define FB 160          // fill blocks appended to kernel A

// ---- device scratch (no allocations; .bss zero at load, kernels self-clean) ----
__device__ unsigned g_h2[(size_t)N_MAX * 64];  // h' rows as packed half2 (64 uints/row)
__device__ int   g_cnt[N_MAX];             // in-degree (excl. self); zeroed by k_final
__device__ float g_dis[N_MAX];             // rsqrt(1 + cnt)
__device__ int   g_start[N_MAX];
__device__ int   g_cursor[N_MAX];
__device__ int   g_adj[E_MAX];
__device__ int   g_total;                  // ticket; zeroed by k_final
__device__ float g_colstats[2 * D];        // zeroed by k_count

__device__ __forceinline__ float4 h8_to_f4(uint2 u) {
    float2 a = __half22float2(*(__half2*)&u.x);
    float2 b = __half22float2(*(__half2*)&u.y);
    return make_float4(a.x, a.y, b.x, b.y);
}

// ---------------------------------------------------------------------------
// K1: in-degree count (grid-stride); block 0 zeros column stats
// ---------------------------------------------------------------------------
__global__ void k_count(const int* __restrict__ pos, int E) {
    if (blockIdx.x == 0) g_colstats[threadIdx.x] = 0.0f;   // 256 == 2*D
    for (int e = blockIdx.x * 256 + threadIdx.x; e < E; e += gridDim.x * 256)
        atomicAdd(&g_cnt[pos[(size_t)E + e]], 1);
}

// ---------------------------------------------------------------------------
// K2: segment allocation — block scan + one atomic ticket; dis; cursor
// ---------------------------------------------------------------------------
__global__ void k_alloc(int N) {
    __shared__ int sh[256];
    __shared__ int base;
    int t = threadIdx.x;
    int i = blockIdx.x * 256 + t;
    int c = (i < N) ? g_cnt[i] : 0;
    sh[t] = c;
    __syncthreads();
    for (int off = 1; off < 256; off <<= 1) {
        int v = (t >= off) ? sh[t - off] : 0;
        __syncthreads();
        sh[t] += v;
        __syncthreads();
    }
    if (t == 255) base = atomicAdd(&g_total, sh[255]);
    __syncthreads();
    if (i < N) {
        int start = base + sh[t] - c;
        g_start[i]  = start;
        g_cursor[i] = start;
        g_dis[i]    = rsqrtf(1.0f + (float)c);
    }
}

// ---------------------------------------------------------------------------
// Kernel A (block-specialized):
//   blocks [0, GB)     : h' = dis[r] * (x @ W)  (fp32x2 GEMM, 128x128 tile)
//                        epilogue packs to half2 -> g_h2
//   blocks [GB, GB+FB) : CSC adjacency fill (independent of h)
// ---------------------------------------------------------------------------
#define FMA2(acc, a, b) asm("fma.rn.f32x2 %0, %1, %2, %0;" : "+l"(acc) : "l"(a), "l"(b))

__global__ void __launch_bounds__(256) kA(const float* __restrict__ x,
                                          const float* __restrict__ W,
                                          const int* __restrict__ pos,
                                          int N, int E, int GB) {
    if (blockIdx.x >= GB) {
        // ---- fill path ----
        int b = blockIdx.x - GB;
        for (int e = b * 256 + threadIdx.x; e < E; e += FB * 256) {
            int col = pos[(size_t)E + e];
            int p = atomicAdd(&g_cursor[col], 1);
            g_adj[p] = pos[e];
        }
        return;
    }

    // ---- GEMM path ----
    __shared__ float xs[16][128];   // transposed x tile
    __shared__ float ws[16][128];   // W tile

    const int t  = threadIdx.x;
    const int r0 = blockIdx.x * 128;
    const int cg = t & 15;
    const int rg = t >> 4;

    unsigned long long acc[8][4];
#pragma unroll
    for (int i = 0; i < 8; i++)
#pragma unroll
        for (int j = 0; j < 4; j++) acc[i][j] = 0ull;

    for (int k0 = 0; k0 < D; k0 += 16) {
        __syncthreads();
#pragma unroll
        for (int u = 0; u < 2; u++) {
            int id  = t + u * 256;
            int row = id >> 2;
            int kq  = (id & 3) * 4;
            float4 v = make_float4(0.f, 0.f, 0.f, 0.f);
            int gr = r0 + row;
            if (gr < N) v = *(const float4*)(x + (size_t)gr * D + k0 + kq);
            xs[kq + 0][row] = v.x;
            xs[kq + 1][row] = v.y;
            xs[kq + 2][row] = v.z;
            xs[kq + 3][row] = v.w;
        }
#pragma unroll
        for (int u = 0; u < 2; u++) {
            int id = t + u * 256;
            int kk = id >> 5;
            int c4 = id & 31;
            *(float4*)&ws[kk][c4 * 4] =
                *(const float4*)(W + (size_t)(k0 + kk) * D + c4 * 4);
        }
        __syncthreads();

#pragma unroll
        for (int kk = 0; kk < 16; kk++) {
            ulonglong2 wA = *(const ulonglong2*)&ws[kk][cg * 8];
            ulonglong2 wB = *(const ulonglong2*)&ws[kk][cg * 8 + 4];
            float4 xa = *(const float4*)&xs[kk][rg * 8];
            float4 xb = *(const float4*)&xs[kk][rg * 8 + 4];
            float xv[8] = {xa.x, xa.y, xa.z, xa.w, xb.x, xb.y, xb.z, xb.w};
#pragma unroll
            for (int i = 0; i < 8; i++) {
                unsigned long long xd;
                asm("mov.b64 %0, {%1, %1};" : "=l"(xd) : "f"(xv[i]));
                FMA2(acc[i][0], xd, wA.x);
                FMA2(acc[i][1], xd, wA.y);
                FMA2(acc[i][2], xd, wB.x);
                FMA2(acc[i][3], xd, wB.y);
            }
        }
    }

#pragma unroll
    for (int i = 0; i < 8; i++) {
        int gr = r0 + rg * 8 + i;
        if (gr < N) {
            float s = g_dis[gr];
            float2 p0 = *(float2*)&acc[i][0];
            float2 p1 = *(float2*)&acc[i][1];
            float2 p2 = *(float2*)&acc[i][2];
            float2 p3 = *(float2*)&acc[i][3];
            __half2 h0 = __floats2half2_rn(p0.x * s, p0.y * s);
            __half2 h1 = __floats2half2_rn(p1.x * s, p1.y * s);
            __half2 h2 = __floats2half2_rn(p2.x * s, p2.y * s);
            __half2 h3 = __floats2half2_rn(p3.x * s, p3.y * s);
            uint4 pk = make_uint4(*(unsigned*)&h0, *(unsigned*)&h1,
                                  *(unsigned*)&h2, *(unsigned*)&h3);
            *(uint4*)(g_h2 + (size_t)gr * 64 + cg * 4) = pk;
        }
    }
}

// ---------------------------------------------------------------------------
// K3: gather — one node per warp; fp16 rows, fp32 accumulation; fused stats.
//     out[c] = dis[c] * (h'[c] + sum_in h'[r])
// ---------------------------------------------------------------------------
__global__ void __launch_bounds__(256, 6) k_gather(float* __restrict__ out, int N) {
    __shared__ float ssum[8][128];
    __shared__ float ssq[8][128];
    int lane = threadIdx.x & 31;
    int w    = threadIdx.x >> 5;

    float4 cs = make_float4(0.f, 0.f, 0.f, 0.f);
    float4 cq = make_float4(0.f, 0.f, 0.f, 0.f);

    for (int node = blockIdx.x * 8 + w; node < N; node += gridDim.x * 8) {
        int start = g_start[node];
        int cnt   = g_cnt[node];

        float4 acc = h8_to_f4(*((const uint2*)(g_h2 + (size_t)node * 64) + lane));

        for (int j = 0; j < cnt; j += 32) {
            int m = min(32, cnt - j);
            int idx = (lane < m) ? g_adj[start + j + lane] : 0;
            int k = 0;
            for (; k + 4 <= m; k += 4) {     // 4-deep MLP
                int rA = __shfl_sync(0xffffffffu, idx, k + 0);
                int rB = __shfl_sync(0xffffffffu, idx, k + 1);
                int rC = __shfl_sync(0xffffffffu, idx, k + 2);
                int rD = __shfl_sync(0xffffffffu, idx, k + 3);
                uint2 uA = *((const uint2*)(g_h2 + (size_t)rA * 64) + lane);
                uint2 uB = *((const uint2*)(g_h2 + (size_t)rB * 64) + lane);
                uint2 uC = *((const uint2*)(g_h2 + (size_t)rC * 64) + lane);
                uint2 uD = *((const uint2*)(g_h2 + (size_t)rD * 64) + lane);
                float4 vA = h8_to_f4(uA);
                float4 vB = h8_to_f4(uB);
                float4 vC = h8_to_f4(uC);
                float4 vD = h8_to_f4(uD);
                acc.x += vA.x + vB.x + vC.x + vD.x;
                acc.y += vA.y + vB.y + vC.y + vD.y;
                acc.z += vA.z + vB.z + vC.z + vD.z;
                acc.w += vA.w + vB.w + vC.w + vD.w;
            }
            for (; k < m; k++) {
                int r = __shfl_sync(0xffffffffu, idx, k);
                float4 v = h8_to_f4(*((const uint2*)(g_h2 + (size_t)r * 64) + lane));
                acc.x += v.x; acc.y += v.y; acc.z += v.z; acc.w += v.w;
            }
        }

        float s = g_dis[node];
        float4 o = make_float4(acc.x * s, acc.y * s, acc.z * s, acc.w * s);
        *(float4*)(out + (size_t)node * D + lane * 4) = o;
        cs.x += o.x; cs.y += o.y; cs.z += o.z; cs.w += o.w;
        cq.x += o.x * o.x; cq.y += o.y * o.y;
        cq.z += o.z * o.z; cq.w += o.w * o.w;
    }

    *(float4*)&ssum[w][lane * 4] = cs;
    *(float4*)&ssq[w][lane * 4]  = cq;
    __syncthreads();
    int t = threadIdx.x;
    if (t < D) {
        float a = 0.f, b = 0.f;
#pragma unroll
        for (int w2 = 0; w2 < 8; w2++) { a += ssum[w2][t]; b += ssq[w2][t]; }
        atomicAdd(&g_colstats[t], a);
        atomicAdd(&g_colstats[D + t], b);
    }
}

// ---------------------------------------------------------------------------
// K4: BN (training mode, biased var) + ReLU in place; 2-way MLP; self-clean
// ---------------------------------------------------------------------------
__global__ void k_final(const float* __restrict__ gamma,
                        const float* __restrict__ beta,
                        float* __restrict__ out, int N) {
    __shared__ float sscale[D], sshift[D];
    int t = threadIdx.x;
    if (t < D) {
        float invN = 1.0f / (float)N;
        float mean = g_colstats[t] * invN;
        float var  = g_colstats[D + t] * invN - mean * mean;
        float inv  = rsqrtf(var + 1e-5f);
        float sc   = gamma[t] * inv;
        sscale[t]  = sc;
        sshift[t]  = beta[t] - mean * sc;
    }
    __syncthreads();

    int gid = blockIdx.x * blockDim.x + t;
    if (gid < N) g_cnt[gid] = 0;
    if (gid == 0) g_total = 0;

    size_t total4 = (size_t)N * (D / 4);
    size_t stride = (size_t)gridDim.x * blockDim.x;
    for (size_t i = (size_t)blockIdx.x * blockDim.x + t; i < total4; i += stride * 2) {
        size_t i2 = i + stride;
        float4 v = ((float4*)out)[i];
        float4 u;
        bool has2 = i2 < total4;
        if (has2) u = ((float4*)out)[i2];
        int c  = (int)(i  & 31) * 4;
        v.x = fmaxf(v.x * sscale[c + 0] + sshift[c + 0], 0.0f);
        v.y = fmaxf(v.y * sscale[c + 1] + sshift[c + 1], 0.0f);
        v.z = fmaxf(v.z * sscale[c + 2] + sshift[c + 2], 0.0f);
        v.w = fmaxf(v.w * sscale[c + 3] + sshift[c + 3], 0.0f);
        ((float4*)out)[i] = v;
        if (has2) {
            int c2 = (int)(i2 & 31) * 4;
            u.x = fmaxf(u.x * sscale[c2 + 0] + sshift[c2 + 0], 0.0f);
            u.y = fmaxf(u.y * sscale[c2 + 1] + sshift[c2 + 1], 0.0f);
            u.z = fmaxf(u.z * sscale[c2 + 2] + sshift[c2 + 2], 0.0f);
            u.w = fmaxf(u.w * sscale[c2 + 3] + sshift[c2 + 3], 0.0f);
            ((float4*)out)[i2] = u;
        }
    }
}

// ---------------------------------------------------------------------------
extern "C" void kernel_launch(void* const* d_in, const int* in_sizes, int n_in,
                              void* d_out, int out_size) {
    const float* x     = (const float*)d_in[0];
    const int*   pos   = (const int*)d_in[1];   // int32 (JAX canonicalizes int64)
    // d_in[2] = neg_edge_index: weight 0 => no-op, skipped
    const float* W     = (const float*)d_in[3];
    // d_in[4] = b: cancels exactly inside BatchNorm, skipped
    const float* gamma = (const float*)d_in[5];
    const float* beta  = (const float*)d_in[6];
    float*       out   = (float*)d_out;

    const int N  = in_sizes[0] / D;
    const int E  = in_sizes[1] / 2;
    const int GB = (N + 127) / 128;

    k_count <<<256, 256>>>(pos, E);
    k_alloc <<<(N + 255) / 256, 256>>>(N);
    kA      <<<GB + FB, 256>>>(x, W, pos, N, E, GB);
    k_gather<<<888, 256>>>(out, N);     // 148 SMs x 6 blocks
    k_final <<<784, 256>>>(gamma, beta, out, N);
}

// round 14
// speedup vs baseline: 1.2305x; 1.0308x over previous
#include <cuda_runtime.h>
#include <cuda_fp16.h>
#include <cstdint>

#define D 128
#define N_MAX 50064
#define E_MAX 500000
#define FB 160          // fill blocks appended to kernel A

// ---- device scratch (no allocations; .bss zero at load, kernels self-clean) ----
__device__ unsigned g_h2[(size_t)N_MAX * 64];  // h' rows as packed half2 (64 uints/row)
__device__ int   g_cnt[N_MAX];             // in-degree (excl. self); zeroed by k_final
__device__ float g_dis[N_MAX];             // rsqrt(1 + cnt)
__device__ int   g_start[N_MAX];
__device__ int   g_cursor[N_MAX];
__device__ int   g_adj[E_MAX];
__device__ int   g_total;                  // ticket; zeroed by k_final
__device__ float g_colstats[2 * D];        // zeroed by k_count

__device__ __forceinline__ float4 h8_to_f4(uint2 u) {
    float2 a = __half22float2(*(__half2*)&u.x);
    float2 b = __half22float2(*(__half2*)&u.y);
    return make_float4(a.x, a.y, b.x, b.y);
}

// ---------------------------------------------------------------------------
// K1: in-degree count (grid-stride); block 0 zeros column stats
// ---------------------------------------------------------------------------
__global__ void k_count(const int* __restrict__ pos, int E) {
    if (blockIdx.x == 0) g_colstats[threadIdx.x] = 0.0f;   // 256 == 2*D
    for (int e = blockIdx.x * 256 + threadIdx.x; e < E; e += gridDim.x * 256)
        atomicAdd(&g_cnt[pos[(size_t)E + e]], 1);
}

// ---------------------------------------------------------------------------
// K2: segment allocation — block scan + one atomic ticket; dis; cursor
// ---------------------------------------------------------------------------
__global__ void k_alloc(int N) {
    __shared__ int sh[256];
    __shared__ int base;
    int t = threadIdx.x;
    int i = blockIdx.x * 256 + t;
    int c = (i < N) ? g_cnt[i] : 0;
    sh[t] = c;
    __syncthreads();
    for (int off = 1; off < 256; off <<= 1) {
        int v = (t >= off) ? sh[t - off] : 0;
        __syncthreads();
        sh[t] += v;
        __syncthreads();
    }
    if (t == 255) base = atomicAdd(&g_total, sh[255]);
    __syncthreads();
    if (i < N) {
        int start = base + sh[t] - c;
        g_start[i]  = start;
        g_cursor[i] = start;
        g_dis[i]    = rsqrtf(1.0f + (float)c);
    }
}

// ---------------------------------------------------------------------------
// Kernel A (block-specialized):
//   blocks [0, GB)     : h' = dis[r] * (x @ W)  (fp32x2 GEMM, 128x128 tile)
//                        epilogue packs to half2 -> g_h2
//   blocks [GB, GB+FB) : CSC adjacency fill (independent of h)
// ---------------------------------------------------------------------------
#define FMA2(acc, a, b) asm("fma.rn.f32x2 %0, %1, %2, %0;" : "+l"(acc) : "l"(a), "l"(b))

__global__ void __launch_bounds__(256) kA(const float* __restrict__ x,
                                          const float* __restrict__ W,
                                          const int* __restrict__ pos,
                                          int N, int E, int GB) {
    if (blockIdx.x >= GB) {
        // ---- fill path ----
        int b = blockIdx.x - GB;
        for (int e = b * 256 + threadIdx.x; e < E; e += FB * 256) {
            int col = pos[(size_t)E + e];
            int p = atomicAdd(&g_cursor[col], 1);
            g_adj[p] = pos[e];
        }
        return;
    }

    // ---- GEMM path ----
    __shared__ float xs[16][128];   // transposed x tile
    __shared__ float ws[16][128];   // W tile

    const int t  = threadIdx.x;
    const int r0 = blockIdx.x * 128;
    const int cg = t & 15;
    const int rg = t >> 4;

    unsigned long long acc[8][4];
#pragma unroll
    for (int i = 0; i < 8; i++)
#pragma unroll
        for (int j = 0; j < 4; j++) acc[i][j] = 0ull;

    for (int k0 = 0; k0 < D; k0 += 16) {
        __syncthreads();
#pragma unroll
        for (int u = 0; u < 2; u++) {
            int id  = t + u * 256;
            int row = id >> 2;
            int kq  = (id & 3) * 4;
            float4 v = make_float4(0.f, 0.f, 0.f, 0.f);
            int gr = r0 + row;
            if (gr < N) v = *(const float4*)(x + (size_t)gr * D + k0 + kq);
            xs[kq + 0][row] = v.x;
            xs[kq + 1][row] = v.y;
            xs[kq + 2][row] = v.z;
            xs[kq + 3][row] = v.w;
        }
#pragma unroll
        for (int u = 0; u < 2; u++) {
            int id = t + u * 256;
            int kk = id >> 5;
            int c4 = id & 31;
            *(float4*)&ws[kk][c4 * 4] =
                *(const float4*)(W + (size_t)(k0 + kk) * D + c4 * 4);
        }
        __syncthreads();

#pragma unroll
        for (int kk = 0; kk < 16; kk++) {
            ulonglong2 wA = *(const ulonglong2*)&ws[kk][cg * 8];
            ulonglong2 wB = *(const ulonglong2*)&ws[kk][cg * 8 + 4];
            float4 xa = *(const float4*)&xs[kk][rg * 8];
            float4 xb = *(const float4*)&xs[kk][rg * 8 + 4];
            float xv[8] = {xa.x, xa.y, xa.z, xa.w, xb.x, xb.y, xb.z, xb.w};
#pragma unroll
            for (int i = 0; i < 8; i++) {
                unsigned long long xd;
                asm("mov.b64 %0, {%1, %1};" : "=l"(xd) : "f"(xv[i]));
                FMA2(acc[i][0], xd, wA.x);
                FMA2(acc[i][1], xd, wA.y);
                FMA2(acc[i][2], xd, wB.x);
                FMA2(acc[i][3], xd, wB.y);
            }
        }
    }

#pragma unroll
    for (int i = 0; i < 8; i++) {
        int gr = r0 + rg * 8 + i;
        if (gr < N) {
            float s = g_dis[gr];
            float2 p0 = *(float2*)&acc[i][0];
            float2 p1 = *(float2*)&acc[i][1];
            float2 p2 = *(float2*)&acc[i][2];
            float2 p3 = *(float2*)&acc[i][3];
            __half2 h0 = __floats2half2_rn(p0.x * s, p0.y * s);
            __half2 h1 = __floats2half2_rn(p1.x * s, p1.y * s);
            __half2 h2 = __floats2half2_rn(p2.x * s, p2.y * s);
            __half2 h3 = __floats2half2_rn(p3.x * s, p3.y * s);
            uint4 pk = make_uint4(*(unsigned*)&h0, *(unsigned*)&h1,
                                  *(unsigned*)&h2, *(unsigned*)&h3);
            *(uint4*)(g_h2 + (size_t)gr * 64 + cg * 4) = pk;
        }
    }
}

// ---------------------------------------------------------------------------
// K3: gather — one node per warp; fp16 rows; first reduction level in HADD2
//     (pairs), then fp32 accumulation; fused stats.
//     out[c] = dis[c] * (h'[c] + sum_in h'[r])
// ---------------------------------------------------------------------------
__global__ void __launch_bounds__(256, 6) k_gather(float* __restrict__ out, int N) {
    __shared__ float ssum[8][128];
    __shared__ float ssq[8][128];
    int lane = threadIdx.x & 31;
    int w    = threadIdx.x >> 5;

    float4 cs = make_float4(0.f, 0.f, 0.f, 0.f);
    float4 cq = make_float4(0.f, 0.f, 0.f, 0.f);

    for (int node = blockIdx.x * 8 + w; node < N; node += gridDim.x * 8) {
        int start = g_start[node];
        int cnt   = g_cnt[node];

        float4 acc = h8_to_f4(*((const uint2*)(g_h2 + (size_t)node * 64) + lane));

        for (int j = 0; j < cnt; j += 32) {
            int m = min(32, cnt - j);
            int idx = (lane < m) ? g_adj[start + j + lane] : 0;
            int k = 0;
            for (; k + 4 <= m; k += 4) {     // 4-deep MLP; fp16 pair adds
                int rA = __shfl_sync(0xffffffffu, idx, k + 0);
                int rB = __shfl_sync(0xffffffffu, idx, k + 1);
                int rC = __shfl_sync(0xffffffffu, idx, k + 2);
                int rD = __shfl_sync(0xffffffffu, idx, k + 3);
                uint2 uA = *((const uint2*)(g_h2 + (size_t)rA * 64) + lane);
                uint2 uB = *((const uint2*)(g_h2 + (size_t)rB * 64) + lane);
                uint2 uC = *((const uint2*)(g_h2 + (size_t)rC * 64) + lane);
                uint2 uD = *((const uint2*)(g_h2 + (size_t)rD * 64) + lane);
                uint2 pAB, pCD;
                *(__half2*)&pAB.x = __hadd2(*(__half2*)&uA.x, *(__half2*)&uB.x);
                *(__half2*)&pAB.y = __hadd2(*(__half2*)&uA.y, *(__half2*)&uB.y);
                *(__half2*)&pCD.x = __hadd2(*(__half2*)&uC.x, *(__half2*)&uD.x);
                *(__half2*)&pCD.y = __hadd2(*(__half2*)&uC.y, *(__half2*)&uD.y);
                float4 vAB = h8_to_f4(pAB);
                float4 vCD = h8_to_f4(pCD);
                acc.x += vAB.x + vCD.x;
                acc.y += vAB.y + vCD.y;
                acc.z += vAB.z + vCD.z;
                acc.w += vAB.w + vCD.w;
            }
            for (; k < m; k++) {
                int r = __shfl_sync(0xffffffffu, idx, k);
                float4 v = h8_to_f4(*((const uint2*)(g_h2 + (size_t)r * 64) + lane));
                acc.x += v.x; acc.y += v.y; acc.z += v.z; acc.w += v.w;
            }
        }

        float s = g_dis[node];
        float4 o = make_float4(acc.x * s, acc.y * s, acc.z * s, acc.w * s);
        *(float4*)(out + (size_t)node * D + lane * 4) = o;
        cs.x += o.x; cs.y += o.y; cs.z += o.z; cs.w += o.w;
        cq.x += o.x * o.x; cq.y += o.y * o.y;
        cq.z += o.z * o.z; cq.w += o.w * o.w;
    }

    *(float4*)&ssum[w][lane * 4] = cs;
    *(float4*)&ssq[w][lane * 4]  = cq;
    __syncthreads();
    int t = threadIdx.x;
    if (t < D) {
        float a = 0.f, b = 0.f;
#pragma unroll
        for (int w2 = 0; w2 < 8; w2++) { a += ssum[w2][t]; b += ssq[w2][t]; }
        atomicAdd(&g_colstats[t], a);
        atomicAdd(&g_colstats[D + t], b);
    }
}

// ---------------------------------------------------------------------------
// K4: BN (training mode, biased var) + ReLU in place; 2-way MLP; self-clean
// ---------------------------------------------------------------------------
__global__ void k_final(const float* __restrict__ gamma,
                        const float* __restrict__ beta,
                        float* __restrict__ out, int N) {
    __shared__ float sscale[D], sshift[D];
    int t = threadIdx.x;
    if (t < D) {
        float invN = 1.0f / (float)N;
        float mean = g_colstats[t] * invN;
        float var  = g_colstats[D + t] * invN - mean * mean;
        float inv  = rsqrtf(var + 1e-5f);
        float sc   = gamma[t] * inv;
        sscale[t]  = sc;
        sshift[t]  = beta[t] - mean * sc;
    }
    __syncthreads();

    int gid = blockIdx.x * blockDim.x + t;
    if (gid < N) g_cnt[gid] = 0;
    if (gid == 0) g_total = 0;

    size_t total4 = (size_t)N * (D / 4);
    size_t stride = (size_t)gridDim.x * blockDim.x;
    for (size_t i = (size_t)blockIdx.x * blockDim.x + t; i < total4; i += stride * 2) {
        size_t i2 = i + stride;
        float4 v = ((float4*)out)[i];
        float4 u;
        bool has2 = i2 < total4;
        if (has2) u = ((float4*)out)[i2];
        int c  = (int)(i  & 31) * 4;
        v.x = fmaxf(v.x * sscale[c + 0] + sshift[c + 0], 0.0f);
        v.y = fmaxf(v.y * sscale[c + 1] + sshift[c + 1], 0.0f);
        v.z = fmaxf(v.z * sscale[c + 2] + sshift[c + 2], 0.0f);
        v.w = fmaxf(v.w * sscale[c + 3] + sshift[c + 3], 0.0f);
        ((float4*)out)[i] = v;
        if (has2) {
            int c2 = (int)(i2 & 31) * 4;
            u.x = fmaxf(u.x * sscale[c2 + 0] + sshift[c2 + 0], 0.0f);
            u.y = fmaxf(u.y * sscale[c2 + 1] + sshift[c2 + 1], 0.0f);
            u.z = fmaxf(u.z * sscale[c2 + 2] + sshift[c2 + 2], 0.0f);
            u.w = fmaxf(u.w * sscale[c2 + 3] + sshift[c2 + 3], 0.0f);
            ((float4*)out)[i2] = u;
        }
    }
}

// ---------------------------------------------------------------------------
extern "C" void kernel_launch(void* const* d_in, const int* in_sizes, int n_in,
                              void* d_out, int out_size) {
    const float* x     = (const float*)d_in[0];
    const int*   pos   = (const int*)d_in[1];   // int32 (JAX canonicalizes int64)
    // d_in[2] = neg_edge_index: weight 0 => no-op, skipped
    const float* W     = (const float*)d_in[3];
    // d_in[4] = b: cancels exactly inside BatchNorm, skipped
    const float* gamma = (const float*)d_in[5];
    const float* beta  = (const float*)d_in[6];
    float*       out   = (float*)d_out;

    const int N  = in_sizes[0] / D;
    const int E  = in_sizes[1] / 2;
    const int GB = (N + 127) / 128;

    k_count <<<256, 256>>>(pos, E);
    k_alloc <<<(N + 255) / 256, 256>>>(N);
    kA      <<<GB + FB, 256>>>(x, W, pos, N, E, GB);
    k_gather<<<888, 256>>>(out, N);     // 148 SMs x 6 blocks
    k_final <<<1184, 256>>>(gamma, beta, out, N);
}